// round 7
// baseline (speedup 1.0000x reference)
#include <cuda_runtime.h>
#include <math_constants.h>

// TropicalLinear forward: out[n,o] = max_j( x[n,j] + w[o,j] ) + bias[o]
//
// 128 blocks x 512 threads. In-block split-K: 4 groups x 128 threads; group g
// covers k in [256g, 256g+256) of the SAME 32x32 output tile, 2x4 accs/thread.
// Final in-kernel smem max-reduction across groups (no combine kernel).
// Double-buffered smem, 64 k's staged per iter (16 granules/row), padded row
// stride 68 floats (17 granules, odd -> conflict-free, immediate LDS offsets).

#define N_DIM   128
#define IN_DIM  1024
#define OUT_DIM 1024
#define BMT     32            // n rows per block tile
#define BOT     32            // o cols per block tile
#define BKT     64            // k staged per iteration (whole block)
#define NITER   (IN_DIM / BKT) // 16
#define STR     68            // smem row stride in floats

__global__ __launch_bounds__(512, 1)
void tropical_kernel(const float* __restrict__ x,
                     const float* __restrict__ w,
                     const float* __restrict__ bias,
                     float* __restrict__ out)
{
    __shared__ float xs[2][BMT * STR];   // 17408 B
    __shared__ float ws[2][BOT * STR];   // 17408 B

    const int t    = threadIdx.x;
    const int g    = t >> 7;          // k-group 0..3
    const int gtid = t & 127;
    const int tx   = gtid & 7;        // o cols: tx, tx+8, tx+16, tx+24
    const int ty   = gtid >> 3;       // n rows: ty, ty+16
    const int oBase = blockIdx.x * BOT;
    const int nBase = blockIdx.y * BMT;

    // loader mapping: 512 threads stage 32 rows x 16 granules per tile
    const int lrow = t >> 4;          // 0..31
    const int lc   = (t & 15) << 2;   // float offset of granule 0..15
    const float* xg = x + (nBase + lrow) * IN_DIM + lc;
    const float* wg = w + (oBase + lrow) * IN_DIM + lc;
    const int sidx = lrow * STR + lc;

    // NOTE: group g's k-slice is interleaved across iters: iter i covers
    // global k [i*64, i*64+64); within that, group g reads floats [16g,16g+16).
    // Over 16 iters each group sees 256 distinct k's -> union covers all 1024.
    const int goff = g << 4;          // float offset of group slice in a row

    float acc[2][4];
#pragma unroll
    for (int r = 0; r < 2; r++)
#pragma unroll
        for (int c = 0; c < 4; c++)
            acc[r][c] = -CUDART_INF_F;

    float4 xr, wr;

    // ---- prologue: tile 0 -> buffer 0 ----
    xr = *(const float4*)xg;
    wr = *(const float4*)wg;
    *(float4*)&xs[0][sidx] = xr;
    *(float4*)&ws[0][sidx] = wr;
    __syncthreads();

#pragma unroll 1
    for (int i = 0; i < NITER - 1; i++) {
        const int b = i & 1;

        // prefetch next 64-k slab (LDG latency hidden under compute)
        xr = *(const float4*)(xg + (i + 1) * BKT);
        wr = *(const float4*)(wg + (i + 1) * BKT);

        const float* px0 = &xs[b][ty * STR + goff];
        const float* px1 = px0 + 16 * STR;
        const float* pw0 = &ws[b][tx * STR + goff];
#pragma unroll
        for (int k4 = 0; k4 < 4; k4++) {
            const float4 a0 = *(const float4*)(px0 + (k4 << 2));
            const float4 a1 = *(const float4*)(px1 + (k4 << 2));
            const float4 b0 = *(const float4*)(pw0 + (k4 << 2));
            const float4 b1 = *(const float4*)(pw0 + 8 * STR  + (k4 << 2));
            const float4 b2 = *(const float4*)(pw0 + 16 * STR + (k4 << 2));
            const float4 b3 = *(const float4*)(pw0 + 24 * STR + (k4 << 2));
#define STEP(A, B, ACC) \
            ACC = fmaxf(ACC, A.x + B.x); ACC = fmaxf(ACC, A.y + B.y); \
            ACC = fmaxf(ACC, A.z + B.z); ACC = fmaxf(ACC, A.w + B.w);
            STEP(a0, b0, acc[0][0]) STEP(a0, b1, acc[0][1])
            STEP(a0, b2, acc[0][2]) STEP(a0, b3, acc[0][3])
            STEP(a1, b0, acc[1][0]) STEP(a1, b1, acc[1][1])
            STEP(a1, b2, acc[1][2]) STEP(a1, b3, acc[1][3])
        }

        const int nb = b ^ 1;
        *(float4*)&xs[nb][sidx] = xr;
        *(float4*)&ws[nb][sidx] = wr;
        __syncthreads();
    }

    // ---- final tile (buffer (NITER-1)&1 = 1) ----
    {
        const float* px0 = &xs[1][ty * STR + goff];
        const float* px1 = px0 + 16 * STR;
        const float* pw0 = &ws[1][tx * STR + goff];
#pragma unroll
        for (int k4 = 0; k4 < 4; k4++) {
            const float4 a0 = *(const float4*)(px0 + (k4 << 2));
            const float4 a1 = *(const float4*)(px1 + (k4 << 2));
            const float4 b0 = *(const float4*)(pw0 + (k4 << 2));
            const float4 b1 = *(const float4*)(pw0 + 8 * STR  + (k4 << 2));
            const float4 b2 = *(const float4*)(pw0 + 16 * STR + (k4 << 2));
            const float4 b3 = *(const float4*)(pw0 + 24 * STR + (k4 << 2));
            STEP(a0, b0, acc[0][0]) STEP(a0, b1, acc[0][1])
            STEP(a0, b2, acc[0][2]) STEP(a0, b3, acc[0][3])
            STEP(a1, b0, acc[1][0]) STEP(a1, b1, acc[1][1])
            STEP(a1, b2, acc[1][2]) STEP(a1, b3, acc[1][3])
#undef STEP
        }
    }

    // ---- cross-group max reduction in smem (reuse xs storage) ----
    __syncthreads();                       // everyone done reading tiles
    float* red = &xs[0][0];                // 4 groups x 32n x 33 floats = 16896 B
    const int rbase = g * (BMT * 33);
#pragma unroll
    for (int r = 0; r < 2; r++)
#pragma unroll
        for (int c = 0; c < 4; c++)
            red[rbase + (ty + 16 * r) * 33 + (tx + 8 * c)] = acc[r][c];
    __syncthreads();

#pragma unroll
    for (int j = 0; j < 2; j++) {
        const int idx = t + j * 512;       // 0..1023
        const int n = idx >> 5;
        const int o = idx & 31;
        const int ro = n * 33 + o;
        float v = fmaxf(fmaxf(red[ro],                red[ro + BMT * 33]),
                        fmaxf(red[ro + 2 * BMT * 33], red[ro + 3 * BMT * 33]));
        out[(nBase + n) * OUT_DIM + oBase + o] = v + bias[oBase + o];
    }
}

extern "C" void kernel_launch(void* const* d_in, const int* in_sizes, int n_in,
                              void* d_out, int out_size)
{
    const float* x    = (const float*)d_in[0];   // [128, 1024]
    const float* w    = (const float*)d_in[1];   // [1024, 1024]
    const float* bias = (const float*)d_in[2];   // [1024]
    float* out = (float*)d_out;                  // [128, 1024]

    dim3 grid(OUT_DIM / BOT, N_DIM / BMT);       // 32 x 4 = 128 blocks
    tropical_kernel<<<grid, 512>>>(x, w, bias, out);
}

// round 8
// speedup vs baseline: 1.6996x; 1.6996x over previous
#include <cuda_runtime.h>
#include <math_constants.h>

// TropicalLinear forward: out[n,o] = max_j( x[n,j] + w[o,j] ) + bias[o]
//
// 128 blocks x 512 threads. Block tile 32n x 32o, full K=1024.
// 16 k-groups (one warp each): warp g handles 16B-granule g of each staged
// 64-k slab (64 k's total), computing the WHOLE 32x32 tile with a 4x8
// register tile per thread (key: 2(R+C)/RC = 0.75 crossbar fraction, vs 2.0
// for the old 2x2 tiles -- LDS.128 costs 4 crossbar cycles regardless of
// broadcast, so fat tiles are the only way off the crossbar).
// In-kernel 16->8->1 smem max-reduction. One smem arena, reused.

#define N_DIM   128
#define IN_DIM  1024
#define OUT_DIM 1024
#define BMT     32
#define BOT     32
#define BKT     64              // k staged per iteration
#define NITER   (IN_DIM / BKT)  // 16
#define TSTR    68              // tile row stride in floats (17 granules, odd)
#define TBUF    (BMT * TSTR)    // 2176 floats per tile buffer
#define RSTR    36              // reduction row stride (36 mod 32 = 4 -> 4ty+tx distinct)
#define RSZ     (BMT * RSTR)    // 1152 floats per partial region

__global__ __launch_bounds__(512, 1)
void tropical_kernel(const float* __restrict__ x,
                     const float* __restrict__ w,
                     const float* __restrict__ bias,
                     float* __restrict__ out)
{
    // arena: tiles (2 bufs x (xs+ws) = 8704 floats) UNION reduction (8 x 1152 = 9216)
    __shared__ float sm[9216];
#define XS(b) (sm + (b) * TBUF)
#define WS(b) (sm + 2 * TBUF + (b) * TBUF)

    const int t    = threadIdx.x;
    const int g    = t >> 5;         // k-group == warp id, 0..15
    const int lane = t & 31;
    const int tx   = lane & 3;       // o cols: tx + 4c, c=0..7
    const int ty   = lane >> 2;      // n rows: ty + 8r, r=0..3
    const int oBase = blockIdx.x * BOT;
    const int nBase = blockIdx.y * BMT;

    // loaders: 512 threads stage 32 rows x 16 granules (one float4 each) per tile
    const int lrow  = t >> 4;        // 0..31
    const int lgran = t & 15;        // granule 0..15
    const float* xg = x + (nBase + lrow) * IN_DIM + (lgran << 2);
    const float* wg = w + (oBase + lrow) * IN_DIM + (lgran << 2);
    const int sidx  = lrow * TSTR + (lgran << 2);

    const int goff = g << 2;         // this group's float offset within a slab row

    float acc[4][8];
#pragma unroll
    for (int r = 0; r < 4; r++)
#pragma unroll
        for (int c = 0; c < 8; c++)
            acc[r][c] = -CUDART_INF_F;

    float4 xr, wr;

    // ---- prologue: slab 0 -> buffer 0 ----
    xr = *(const float4*)xg;
    wr = *(const float4*)wg;
    *(float4*)&XS(0)[sidx] = xr;
    *(float4*)&WS(0)[sidx] = wr;
    __syncthreads();

#define COMPUTE(b)                                                          \
    {                                                                       \
        const float* px = XS(b) + ty * TSTR + goff;                         \
        const float* pw = WS(b) + tx * TSTR + goff;                         \
        float4 a0 = *(const float4*)(px);                                   \
        float4 a1 = *(const float4*)(px + 8 * TSTR);                        \
        float4 a2 = *(const float4*)(px + 16 * TSTR);                       \
        float4 a3 = *(const float4*)(px + 24 * TSTR);                       \
        float4 bv;                                                          \
        _Pragma("unroll")                                                   \
        for (int c = 0; c < 8; c++) {                                       \
            bv = *(const float4*)(pw + c * (4 * TSTR));                     \
            acc[0][c] = fmaxf(acc[0][c], a0.x + bv.x);                      \
            acc[0][c] = fmaxf(acc[0][c], a0.y + bv.y);                      \
            acc[0][c] = fmaxf(acc[0][c], a0.z + bv.z);                      \
            acc[0][c] = fmaxf(acc[0][c], a0.w + bv.w);                      \
            acc[1][c] = fmaxf(acc[1][c], a1.x + bv.x);                      \
            acc[1][c] = fmaxf(acc[1][c], a1.y + bv.y);                      \
            acc[1][c] = fmaxf(acc[1][c], a1.z + bv.z);                      \
            acc[1][c] = fmaxf(acc[1][c], a1.w + bv.w);                      \
            acc[2][c] = fmaxf(acc[2][c], a2.x + bv.x);                      \
            acc[2][c] = fmaxf(acc[2][c], a2.y + bv.y);                      \
            acc[2][c] = fmaxf(acc[2][c], a2.z + bv.z);                      \
            acc[2][c] = fmaxf(acc[2][c], a2.w + bv.w);                      \
            acc[3][c] = fmaxf(acc[3][c], a3.x + bv.x);                      \
            acc[3][c] = fmaxf(acc[3][c], a3.y + bv.y);                      \
            acc[3][c] = fmaxf(acc[3][c], a3.z + bv.z);                      \
            acc[3][c] = fmaxf(acc[3][c], a3.w + bv.w);                      \
        }                                                                   \
    }

#pragma unroll 1
    for (int i = 0; i < NITER - 1; i++) {
        const int b = i & 1;

        // prefetch next slab (LDG latency hidden under 256 math insts)
        xr = *(const float4*)(xg + (i + 1) * BKT);
        wr = *(const float4*)(wg + (i + 1) * BKT);

        COMPUTE(b)

        const int nb = b ^ 1;
        *(float4*)&XS(nb)[sidx] = xr;
        *(float4*)&WS(nb)[sidx] = wr;
        __syncthreads();
    }

    COMPUTE(1)   // slab 15 is in buffer (15 & 1) = 1

    // ---- cross-group reduction: 16 -> 8 -> 1 (reuses the smem arena) ----
    __syncthreads();                       // everyone done reading tiles

    // stage A: groups 8..15 park partials in region g-8
    if (g >= 8) {
        float* red = sm + (g - 8) * RSZ;
#pragma unroll
        for (int r = 0; r < 4; r++)
#pragma unroll
            for (int c = 0; c < 8; c++)
                red[(ty + 8 * r) * RSTR + tx + 4 * c] = acc[r][c];
    }
    __syncthreads();

    // stage B: groups 0..7 merge own accs into region g
    if (g < 8) {
        float* red = sm + g * RSZ;
#pragma unroll
        for (int r = 0; r < 4; r++)
#pragma unroll
            for (int c = 0; c < 8; c++) {
                const int off = (ty + 8 * r) * RSTR + tx + 4 * c;
                red[off] = fmaxf(red[off], acc[r][c]);
            }
    }
    __syncthreads();

    // stage C: 8-way max + bias + store; 1024 outputs / 512 threads = 2 each
#pragma unroll
    for (int j = 0; j < 2; j++) {
        const int idx = t + j * 512;       // 0..1023
        const int n = idx >> 5;
        const int o = idx & 31;
        const int ro = n * RSTR + o;
        float v0 = fmaxf(sm[ro],           sm[ro + RSZ]);
        float v1 = fmaxf(sm[ro + 2 * RSZ], sm[ro + 3 * RSZ]);
        float v2 = fmaxf(sm[ro + 4 * RSZ], sm[ro + 5 * RSZ]);
        float v3 = fmaxf(sm[ro + 6 * RSZ], sm[ro + 7 * RSZ]);
        float v  = fmaxf(fmaxf(v0, v1), fmaxf(v2, v3));
        out[(nBase + n) * OUT_DIM + oBase + o] = v + bias[oBase + o];
    }
}

extern "C" void kernel_launch(void* const* d_in, const int* in_sizes, int n_in,
                              void* d_out, int out_size)
{
    const float* x    = (const float*)d_in[0];   // [128, 1024]
    const float* w    = (const float*)d_in[1];   // [1024, 1024]
    const float* bias = (const float*)d_in[2];   // [1024]
    float* out = (float*)d_out;                  // [128, 1024]

    dim3 grid(OUT_DIM / BOT, N_DIM / BMT);       // 32 x 4 = 128 blocks
    tropical_kernel<<<grid, 512>>>(x, w, bias, out);
}